// round 8
// baseline (speedup 1.0000x reference)
#include <cuda_runtime.h>
#include <cuda_bf16.h>
#include <cstdint>

#define HEADSZ 64
#define EMB    1024
#define BATCH  4
#define SEQ    4096
#define BT     (BATCH*SEQ)

// Scratch (allocation-free)
__device__ __nv_bfloat16 g_Qh[(size_t)BT*HEADSZ];
__device__ __nv_bfloat16 g_Ql[(size_t)BT*HEADSZ];
__device__ __nv_bfloat16 g_Kh[(size_t)BT*HEADSZ];
__device__ __nv_bfloat16 g_Kl[(size_t)BT*HEADSZ];
__device__ __nv_bfloat16 g_Vh[(size_t)BT*EMB];
__device__ __nv_bfloat16 g_Vl[(size_t)BT*EMB];

// ===========================================================================
// helpers
// ===========================================================================
__device__ __forceinline__ uint32_t smem_u32(const void* p) {
    uint32_t a;
    asm("{ .reg .u64 t; cvta.to.shared.u64 t, %1; cvt.u32.u64 %0, t; }"
        : "=r"(a) : "l"(p));
    return a;
}

#define LDMX4(r, a) \
    asm volatile("ldmatrix.sync.aligned.m8n8.x4.shared.b16 {%0,%1,%2,%3}, [%4];" \
        : "=r"((r)[0]), "=r"((r)[1]), "=r"((r)[2]), "=r"((r)[3]) : "r"(a))
#define LDMX4T(r, a) \
    asm volatile("ldmatrix.sync.aligned.m8n8.x4.trans.shared.b16 {%0,%1,%2,%3}, [%4];" \
        : "=r"((r)[0]), "=r"((r)[1]), "=r"((r)[2]), "=r"((r)[3]) : "r"(a))

#define MMA_BF16(d, a, b) \
    asm volatile("mma.sync.aligned.m16n8k16.row.col.f32.bf16.bf16.f32 " \
        "{%0,%1,%2,%3}, {%4,%5,%6,%7}, {%8,%9}, {%0,%1,%2,%3};" \
        : "+f"((d)[0]), "+f"((d)[1]), "+f"((d)[2]), "+f"((d)[3]) \
        : "r"((a)[0]), "r"((a)[1]), "r"((a)[2]), "r"((a)[3]), \
          "r"((b)[0]), "r"((b)[1]))

#define MMA3(d, ah, al, bh, bl) do { \
    MMA_BF16(d, ah, bh); MMA_BF16(d, ah, bl); MMA_BF16(d, al, bh); } while (0)

#define MMA_TF32(d, a, b0, b1) \
    asm volatile("mma.sync.aligned.m16n8k8.row.col.f32.tf32.tf32.f32 " \
        "{%0,%1,%2,%3}, {%4,%5,%6,%7}, {%8,%9}, {%0,%1,%2,%3};" \
        : "+f"((d)[0]), "+f"((d)[1]), "+f"((d)[2]), "+f"((d)[3]) \
        : "r"((a)[0]), "r"((a)[1]), "r"((a)[2]), "r"((a)[3]), \
          "r"(b0), "r"(b1))

#define CPA16(dst, src) \
    asm volatile("cp.async.cg.shared.global [%0], [%1], 16;" :: "r"(dst), "l"(src))
#define CPA_COMMIT() asm volatile("cp.async.commit_group;" ::: "memory")
#define CPA_WAIT(n)  asm volatile("cp.async.wait_group %0;" :: "n"(n) : "memory")

__device__ __forceinline__ uint32_t a_addr(uint32_t base, int row, int kbyte,
                                           int lane, int strideB) {
    return base + (uint32_t)(row + (lane & 15)) * strideB + kbyte +
           ((lane >> 4) << 4);
}

__device__ __forceinline__ uint32_t bpack(__nv_bfloat16 a, __nv_bfloat16 b) {
    return ((uint32_t)__bfloat16_as_ushort(b) << 16) |
           (uint32_t)__bfloat16_as_ushort(a);
}
__device__ __forceinline__ uint32_t packsplit2(float a, float b, uint32_t& lo) {
    __nv_bfloat16 ha = __float2bfloat16_rn(a), hb = __float2bfloat16_rn(b);
    lo = bpack(__float2bfloat16_rn(a - __bfloat162float(ha)),
               __float2bfloat16_rn(b - __bfloat162float(hb)));
    return bpack(ha, hb);
}
__device__ __forceinline__ uint32_t f2tf32(float x) {
    uint32_t u;
    asm("cvt.rna.tf32.f32 %0, %1;" : "=r"(u) : "f"(x));
    return u;
}

// ===========================================================================
// Fused projections (tf32 m16n8k8): V = x@Wv^T for all CTAs;
// blockIdx.x==0 CTAs additionally compute K = x@Wk^T, Q = x@Wq^T.
// Tile 128x128, BK=32, 256 threads. All outputs split bf16 hi/lo.
// ===========================================================================
#define VP_SMEM (3 * 128 * 36 * 4)      // As, Bs, QKBs : 55296

__global__ __launch_bounds__(256, 1) void proj_tf32(
    const float* __restrict__ A, const float* __restrict__ W,
    const float* __restrict__ Wk, const float* __restrict__ Wq,
    __nv_bfloat16* __restrict__ Vh, __nv_bfloat16* __restrict__ Vl,
    __nv_bfloat16* __restrict__ Kh, __nv_bfloat16* __restrict__ Kl,
    __nv_bfloat16* __restrict__ Qh, __nv_bfloat16* __restrict__ Ql)
{
    extern __shared__ char sm[];
    uint32_t* As  = (uint32_t*)sm;           // [128][36]
    uint32_t* Bs  = As + 128*36;             // [128][36]
    uint32_t* QKs = Bs + 128*36;             // [128][36]
    const int tid = threadIdx.x, wid = tid >> 5, lane = tid & 31;
    const int g = lane >> 2, t = lane & 3;
    const int row0 = blockIdx.y * 128;
    const int col0 = blockIdx.x * 128;
    const bool doqk = (blockIdx.x == 0);
    const int m0 = (wid & 3) * 32, n0 = (wid >> 2) * 64;

    float o[16][4], o2[16][4];
    #pragma unroll
    for (int i = 0; i < 16; i++)
        #pragma unroll
        for (int j = 0; j < 4; j++) { o[i][j] = 0.f; o2[i][j] = 0.f; }

    const int lr = tid >> 1, lc0 = (tid & 1) * 16;
    const float* arow = A + (size_t)(row0 + lr) * EMB + lc0;
    const float* brow = W + (size_t)(col0 + lr) * EMB + lc0;
    const float* qkrow = (lr < 64 ? Wk + (size_t)lr * EMB
                                  : Wq + (size_t)(lr - 64) * EMB) + lc0;

    for (int kc = 0; kc < EMB / 32; kc++) {
        #pragma unroll
        for (int j = 0; j < 4; j++) {
            float4 va = *(const float4*)(arow + kc * 32 + j * 4);
            As[lr*36 + lc0 + j*4 + 0] = f2tf32(va.x);
            As[lr*36 + lc0 + j*4 + 1] = f2tf32(va.y);
            As[lr*36 + lc0 + j*4 + 2] = f2tf32(va.z);
            As[lr*36 + lc0 + j*4 + 3] = f2tf32(va.w);
            float4 vb = *(const float4*)(brow + kc * 32 + j * 4);
            Bs[lr*36 + lc0 + j*4 + 0] = f2tf32(vb.x);
            Bs[lr*36 + lc0 + j*4 + 1] = f2tf32(vb.y);
            Bs[lr*36 + lc0 + j*4 + 2] = f2tf32(vb.z);
            Bs[lr*36 + lc0 + j*4 + 3] = f2tf32(vb.w);
        }
        if (doqk) {
            #pragma unroll
            for (int j = 0; j < 4; j++) {
                float4 vq = *(const float4*)(qkrow + kc * 32 + j * 4);
                QKs[lr*36 + lc0 + j*4 + 0] = f2tf32(vq.x);
                QKs[lr*36 + lc0 + j*4 + 1] = f2tf32(vq.y);
                QKs[lr*36 + lc0 + j*4 + 2] = f2tf32(vq.z);
                QKs[lr*36 + lc0 + j*4 + 3] = f2tf32(vq.w);
            }
        }
        __syncthreads();
        #pragma unroll
        for (int ks = 0; ks < 4; ks++) {
            uint32_t a[2][4];
            #pragma unroll
            for (int mt = 0; mt < 2; mt++) {
                const int r = m0 + mt*16;
                a[mt][0] = As[(r + g)*36     + ks*8 + t];
                a[mt][1] = As[(r + 8 + g)*36 + ks*8 + t];
                a[mt][2] = As[(r + g)*36     + ks*8 + t + 4];
                a[mt][3] = As[(r + 8 + g)*36 + ks*8 + t + 4];
            }
            #pragma unroll
            for (int nt = 0; nt < 8; nt++) {
                uint32_t b0 = Bs[(n0 + nt*8 + g)*36 + ks*8 + t];
                uint32_t b1 = Bs[(n0 + nt*8 + g)*36 + ks*8 + t + 4];
                #pragma unroll
                for (int mt = 0; mt < 2; mt++)
                    MMA_TF32(o[mt*8 + nt], a[mt], b0, b1);
            }
            if (doqk) {
                #pragma unroll
                for (int nt = 0; nt < 8; nt++) {
                    uint32_t b0 = QKs[(n0 + nt*8 + g)*36 + ks*8 + t];
                    uint32_t b1 = QKs[(n0 + nt*8 + g)*36 + ks*8 + t + 4];
                    #pragma unroll
                    for (int mt = 0; mt < 2; mt++)
                        MMA_TF32(o2[mt*8 + nt], a[mt], b0, b1);
                }
            }
        }
        __syncthreads();
    }

    #pragma unroll
    for (int mt = 0; mt < 2; mt++)
        #pragma unroll
        for (int nt = 0; nt < 8; nt++) {
            const int r0 = row0 + m0 + mt*16 + g;
            const int c  = col0 + n0 + nt*8 + 2*t;
            uint32_t lo0, lo1;
            uint32_t hi0 = packsplit2(o[mt*8+nt][0], o[mt*8+nt][1], lo0);
            uint32_t hi1 = packsplit2(o[mt*8+nt][2], o[mt*8+nt][3], lo1);
            *(uint32_t*)(Vh + (size_t)r0 * EMB + c)       = hi0;
            *(uint32_t*)(Vl + (size_t)r0 * EMB + c)       = lo0;
            *(uint32_t*)(Vh + (size_t)(r0 + 8) * EMB + c) = hi1;
            *(uint32_t*)(Vl + (size_t)(r0 + 8) * EMB + c) = lo1;
        }

    if (doqk) {
        __nv_bfloat16* Ch = (n0 == 0) ? Kh : Qh;
        __nv_bfloat16* Cl = (n0 == 0) ? Kl : Ql;
        #pragma unroll
        for (int mt = 0; mt < 2; mt++)
            #pragma unroll
            for (int nt = 0; nt < 8; nt++) {
                const int r0 = row0 + m0 + mt*16 + g;
                const int c  = nt*8 + 2*t;     // 0..63 within K or Q
                uint32_t lo0, lo1;
                uint32_t hi0 = packsplit2(o2[mt*8+nt][0], o2[mt*8+nt][1], lo0);
                uint32_t hi1 = packsplit2(o2[mt*8+nt][2], o2[mt*8+nt][3], lo1);
                *(uint32_t*)(Ch + (size_t)r0 * HEADSZ + c)       = hi0;
                *(uint32_t*)(Cl + (size_t)r0 * HEADSZ + c)       = lo0;
                *(uint32_t*)(Ch + (size_t)(r0 + 8) * HEADSZ + c) = hi1;
                *(uint32_t*)(Cl + (size_t)(r0 + 8) * HEADSZ + c) = lo1;
            }
    }
}

// ===========================================================================
// Flash attention, register-resident P (FA2 style).
// 256 threads, CTA = 128 q x 128 dims. Warp w owns q rows w*16..w*16+15,
// full 64-key width -> in-warp softmax, S accum -> bf16 hi/lo A-frags in
// registers -> PV directly. 3-stage cp.async K+V pipeline, 1 barrier/tile.
// ===========================================================================
#define AQ_H   0                          // Q hi: 128 x 144B
#define AQ_L   18432                      // Q lo
#define AK     36864                      // K stages: 3 x 18432 (lo at +9216)
#define AV     92160                      // V stages: 3 x 34816 (lo at +17408)
#define A_SMEM 196608

__global__ __launch_bounds__(256, 1) void attn_reg(
    const __nv_bfloat16* __restrict__ Qh, const __nv_bfloat16* __restrict__ Ql,
    const __nv_bfloat16* __restrict__ Kh, const __nv_bfloat16* __restrict__ Kl,
    const __nv_bfloat16* __restrict__ Vh, const __nv_bfloat16* __restrict__ Vl,
    float* __restrict__ out)
{
    extern __shared__ char sm[];
    const uint32_t smb = smem_u32(sm);
    const int tid = threadIdx.x, wid = tid >> 5, lane = tid & 31;
    const int g = lane >> 2, t = lane & 3;
    const int qt = (SEQ/128 - 1) - blockIdx.y;
    const int q0 = qt * 128;
    const int d0 = blockIdx.x * 128;
    const int nkt = 2*qt + 2;
    const size_t tok0 = (size_t)blockIdx.z * SEQ;

    // ---- loaders (256 threads) ----
    auto load_kv = [&](int kt, int stg) {
        const int row = tid >> 2;                        // 0..63
        const size_t key = tok0 + kt*64 + row;
        {   // K: 64 x 128B hi + lo
            const int c = (tid & 3) * 32;
            const char* gh = (const char*)(Kh + key * HEADSZ) + c;
            const char* gl = (const char*)(Kl + key * HEADSZ) + c;
            const uint32_t dk = smb + AK + stg*18432 + row*144 + c;
            CPA16(dk,          gh);
            CPA16(dk + 16,     gh + 16);
            CPA16(dk + 9216,   gl);
            CPA16(dk + 9216 + 16, gl + 16);
        }
        {   // V: 64 x 256B hi + lo (128-dim slice)
            const int c = (tid & 3) * 64;
            const char* gh = (const char*)(Vh + key * EMB + d0) + c;
            const char* gl = (const char*)(Vl + key * EMB + d0) + c;
            const uint32_t dv = smb + AV + stg*34816 + row*272 + c;
            #pragma unroll
            for (int j = 0; j < 4; j++) {
                CPA16(dv + j*16,         gh + j*16);
                CPA16(dv + 17408 + j*16, gl + j*16);
            }
        }
    };

    // ---- prologue: Q + KV0 (G0), KV1 (G1) ----
    {
        const int row = tid >> 1, c = (tid & 1) * 64;
        const char* gh = (const char*)(Qh + (tok0 + q0 + row) * HEADSZ) + c;
        const char* gl = (const char*)(Ql + (tok0 + q0 + row) * HEADSZ) + c;
        const uint32_t dq = smb + AQ_H + row*144 + c;
        #pragma unroll
        for (int j = 0; j < 4; j++) {
            CPA16(dq + j*16,                   gh + j*16);
            CPA16(dq + (AQ_L - AQ_H) + j*16,   gl + j*16);
        }
    }
    load_kv(0, 0);
    CPA_COMMIT();                              // G0
    load_kv(1, 1);
    CPA_COMMIT();                              // G1

    uint32_t qah[4][4], qal[4][4];
    float o[16][4];
    #pragma unroll
    for (int i = 0; i < 16; i++)
        #pragma unroll
        for (int j = 0; j < 4; j++) o[i][j] = 0.f;
    float m0 = -1e30f, m1 = -1e30f, l0 = 0.f, l1 = 0.f;
    const int qr0 = q0 + wid*16 + g, qr1 = qr0 + 8;

    for (int kt = 0; kt < nkt; kt++) {
        const int stg = kt % 3;
        if (kt + 1 < nkt) { CPA_WAIT(1); } else { CPA_WAIT(0); }
        __syncthreads();                       // tile kt ready; kt-1 consumed
        if (kt == 0) {
            #pragma unroll
            for (int ks = 0; ks < 4; ks++) {
                LDMX4(qah[ks], a_addr(smb + AQ_H, wid*16, ks*32, lane, 144));
                LDMX4(qal[ks], a_addr(smb + AQ_L, wid*16, ks*32, lane, 144));
            }
        }
        if (kt + 2 < nkt) {                    // refill stage (kt+2)%3 (= kt-1's)
            load_kv(kt + 2, (kt + 2) % 3);
            CPA_COMMIT();
        }

        // ---- S = Q @ K^T : 16 rows x 64 keys ----
        float s[8][4];
        #pragma unroll
        for (int i = 0; i < 8; i++)
            #pragma unroll
            for (int j = 0; j < 4; j++) s[i][j] = 0.f;
        const uint32_t kb = smb + AK + stg*18432;
        #pragma unroll
        for (int ks = 0; ks < 4; ks++) {
            #pragma unroll
            for (int ntp = 0; ntp < 4; ntp++) {
                uint32_t bh4[4], bl4[4];
                const uint32_t ka = kb +
                    (uint32_t)(ntp*16 + (lane & 7) + ((lane >> 4) << 3)) * 144
                    + ks*32 + (((lane >> 3) & 1) << 4);
                LDMX4(bh4, ka);
                LDMX4(bl4, ka + 9216);
                MMA3(s[2*ntp],     qah[ks], qal[ks], bh4,     bl4);
                MMA3(s[2*ntp + 1], qah[ks], qal[ks], bh4 + 2, bl4 + 2);
            }
        }

        // ---- in-warp online softmax ----
        float mx0 = -1e30f, mx1 = -1e30f;
        #pragma unroll
        for (int nt = 0; nt < 8; nt++) {
            const int c = kt*64 + nt*8 + 2*t;
            s[nt][0] = (c     <= qr0) ? s[nt][0]*0.125f : -1e30f;
            s[nt][1] = (c + 1 <= qr0) ? s[nt][1]*0.125f : -1e30f;
            s[nt][2] = (c     <= qr1) ? s[nt][2]*0.125f : -1e30f;
            s[nt][3] = (c + 1 <= qr1) ? s[nt][3]*0.125f : -1e30f;
            mx0 = fmaxf(mx0, fmaxf(s[nt][0], s[nt][1]));
            mx1 = fmaxf(mx1, fmaxf(s[nt][2], s[nt][3]));
        }
        mx0 = fmaxf(mx0, __shfl_xor_sync(0xffffffffu, mx0, 1));
        mx0 = fmaxf(mx0, __shfl_xor_sync(0xffffffffu, mx0, 2));
        mx1 = fmaxf(mx1, __shfl_xor_sync(0xffffffffu, mx1, 1));
        mx1 = fmaxf(mx1, __shfl_xor_sync(0xffffffffu, mx1, 2));
        const float mn0 = fmaxf(m0, mx0), mn1 = fmaxf(m1, mx1);
        const float sc0 = __expf(m0 - mn0), sc1 = __expf(m1 - mn1);
        float sum0 = 0.f, sum1 = 0.f;
        #pragma unroll
        for (int nt = 0; nt < 8; nt++) {
            s[nt][0] = __expf(s[nt][0] - mn0);
            s[nt][1] = __expf(s[nt][1] - mn0);
            s[nt][2] = __expf(s[nt][2] - mn1);
            s[nt][3] = __expf(s[nt][3] - mn1);
            sum0 += s[nt][0] + s[nt][1];
            sum1 += s[nt][2] + s[nt][3];
        }
        sum0 += __shfl_xor_sync(0xffffffffu, sum0, 1);
        sum0 += __shfl_xor_sync(0xffffffffu, sum0, 2);
        sum1 += __shfl_xor_sync(0xffffffffu, sum1, 1);
        sum1 += __shfl_xor_sync(0xffffffffu, sum1, 2);
        l0 = l0*sc0 + sum0; l1 = l1*sc1 + sum1;
        m0 = mn0; m1 = mn1;

        // ---- pack P A-fragments in registers (hi/lo split) ----
        uint32_t ph[4][4], pl[4][4];
        #pragma unroll
        for (int ks = 0; ks < 4; ks++) {
            ph[ks][0] = packsplit2(s[2*ks][0],     s[2*ks][1],     pl[ks][0]);
            ph[ks][1] = packsplit2(s[2*ks][2],     s[2*ks][3],     pl[ks][1]);
            ph[ks][2] = packsplit2(s[2*ks + 1][0], s[2*ks + 1][1], pl[ks][2]);
            ph[ks][3] = packsplit2(s[2*ks + 1][2], s[2*ks + 1][3], pl[ks][3]);
        }

        // ---- rescale O, O += P @ V ----
        #pragma unroll
        for (int nt = 0; nt < 16; nt++) {
            o[nt][0] *= sc0; o[nt][1] *= sc0;
            o[nt][2] *= sc1; o[nt][3] *= sc1;
        }
        const uint32_t vb = smb + AV + stg*34816;
        #pragma unroll
        for (int ks = 0; ks < 4; ks++) {
            #pragma unroll
            for (int ntp = 0; ntp < 8; ntp++) {
                uint32_t vh4[4], vl4[4];
                const uint32_t va = vb +
                    (uint32_t)(ks*16 + (lane & 7) + (((lane >> 3) & 1) << 3)) * 272
                    + (ntp*16 + ((lane >> 4) << 3)) * 2;
                LDMX4T(vh4, va);
                LDMX4T(vl4, va + 17408);
                MMA3(o[2*ntp],     ph[ks], pl[ks], vh4,     vl4);
                MMA3(o[2*ntp + 1], ph[ks], pl[ks], vh4 + 2, vl4 + 2);
            }
        }
    }

    // ---- normalize + store ----
    const float i0 = 1.f / l0, i1 = 1.f / l1;
    const int r0 = wid*16 + g;
    #pragma unroll
    for (int nt = 0; nt < 16; nt++) {
        const int c = d0 + nt*8 + 2*t;
        float2 v0 = make_float2(o[nt][0]*i0, o[nt][1]*i0);
        float2 v1 = make_float2(o[nt][2]*i1, o[nt][3]*i1);
        *(float2*)(out + (tok0 + q0 + r0)     * EMB + c) = v0;
        *(float2*)(out + (tok0 + q0 + r0 + 8) * EMB + c) = v1;
    }
}

// ===========================================================================
extern "C" void kernel_launch(void* const* d_in, const int* in_sizes, int n_in,
                              void* d_out, int out_size)
{
    const float* x  = (const float*)d_in[0];
    const float* Wk = (const float*)d_in[1];
    const float* Wq = (const float*)d_in[2];
    const float* Wv = (const float*)d_in[3];
    float* out = (float*)d_out;

    __nv_bfloat16 *Qh, *Ql, *Kh, *Kl, *Vh, *Vl;
    cudaGetSymbolAddress((void**)&Qh, g_Qh);
    cudaGetSymbolAddress((void**)&Ql, g_Ql);
    cudaGetSymbolAddress((void**)&Kh, g_Kh);
    cudaGetSymbolAddress((void**)&Kl, g_Kl);
    cudaGetSymbolAddress((void**)&Vh, g_Vh);
    cudaGetSymbolAddress((void**)&Vl, g_Vl);

    cudaFuncSetAttribute(proj_tf32, cudaFuncAttributeMaxDynamicSharedMemorySize, VP_SMEM);
    cudaFuncSetAttribute(attn_reg,  cudaFuncAttributeMaxDynamicSharedMemorySize, A_SMEM);

    // Fused V + QK projections (tf32 tensor)
    proj_tf32<<<dim3(EMB/128, BT/128), 256, VP_SMEM>>>(
        x, Wv, Wk, Wq, Vh, Vl, Kh, Kl, Qh, Ql);

    // Flash attention, register P
    attn_reg<<<dim3(EMB/128, SEQ/128, BATCH), 256, A_SMEM>>>(
        Qh, Ql, Kh, Kl, Vh, Vl, out);
}

// round 10
// speedup vs baseline: 1.0620x; 1.0620x over previous
#include <cuda_runtime.h>
#include <cuda_bf16.h>
#include <cstdint>

#define HEADSZ 64
#define EMB    1024
#define BATCH  4
#define SEQ    4096
#define BT     (BATCH*SEQ)

// Scratch (allocation-free)
__device__ __nv_bfloat16 g_Qh[(size_t)BT*HEADSZ];
__device__ __nv_bfloat16 g_Ql[(size_t)BT*HEADSZ];
__device__ __nv_bfloat16 g_Kh[(size_t)BT*HEADSZ];
__device__ __nv_bfloat16 g_Kl[(size_t)BT*HEADSZ];
__device__ __nv_bfloat16 g_Vh[(size_t)BT*EMB];
__device__ __nv_bfloat16 g_Vl[(size_t)BT*EMB];

// ===========================================================================
// helpers
// ===========================================================================
__device__ __forceinline__ uint32_t smem_u32(const void* p) {
    uint32_t a;
    asm("{ .reg .u64 t; cvta.to.shared.u64 t, %1; cvt.u32.u64 %0, t; }"
        : "=r"(a) : "l"(p));
    return a;
}

#define LDMX4(r, a) \
    asm volatile("ldmatrix.sync.aligned.m8n8.x4.shared.b16 {%0,%1,%2,%3}, [%4];" \
        : "=r"((r)[0]), "=r"((r)[1]), "=r"((r)[2]), "=r"((r)[3]) : "r"(a))
#define LDMX4T(r, a) \
    asm volatile("ldmatrix.sync.aligned.m8n8.x4.trans.shared.b16 {%0,%1,%2,%3}, [%4];" \
        : "=r"((r)[0]), "=r"((r)[1]), "=r"((r)[2]), "=r"((r)[3]) : "r"(a))

#define MMA_BF16(d, a, b) \
    asm volatile("mma.sync.aligned.m16n8k16.row.col.f32.bf16.bf16.f32 " \
        "{%0,%1,%2,%3}, {%4,%5,%6,%7}, {%8,%9}, {%0,%1,%2,%3};" \
        : "+f"((d)[0]), "+f"((d)[1]), "+f"((d)[2]), "+f"((d)[3]) \
        : "r"((a)[0]), "r"((a)[1]), "r"((a)[2]), "r"((a)[3]), \
          "r"((b)[0]), "r"((b)[1]))

#define MMA3(d, ah, al, bh, bl) do { \
    MMA_BF16(d, ah, bh); MMA_BF16(d, ah, bl); MMA_BF16(d, al, bh); } while (0)

#define MMA_TF32(d, a, b0, b1) \
    asm volatile("mma.sync.aligned.m16n8k8.row.col.f32.tf32.tf32.f32 " \
        "{%0,%1,%2,%3}, {%4,%5,%6,%7}, {%8,%9}, {%0,%1,%2,%3};" \
        : "+f"((d)[0]), "+f"((d)[1]), "+f"((d)[2]), "+f"((d)[3]) \
        : "r"((a)[0]), "r"((a)[1]), "r"((a)[2]), "r"((a)[3]), \
          "r"(b0), "r"(b1))

#define CPA16(dst, src) \
    asm volatile("cp.async.cg.shared.global [%0], [%1], 16;" :: "r"(dst), "l"(src))
#define CPA_COMMIT() asm volatile("cp.async.commit_group;" ::: "memory")
#define CPA_WAIT(n)  asm volatile("cp.async.wait_group %0;" :: "n"(n) : "memory")

__device__ __forceinline__ uint32_t a_addr(uint32_t base, int row, int kbyte,
                                           int lane, int strideB) {
    return base + (uint32_t)(row + (lane & 15)) * strideB + kbyte +
           ((lane >> 4) << 4);
}

__device__ __forceinline__ uint32_t bpack(__nv_bfloat16 a, __nv_bfloat16 b) {
    return ((uint32_t)__bfloat16_as_ushort(b) << 16) |
           (uint32_t)__bfloat16_as_ushort(a);
}
__device__ __forceinline__ uint32_t packsplit2(float a, float b, uint32_t& lo) {
    __nv_bfloat16 ha = __float2bfloat16_rn(a), hb = __float2bfloat16_rn(b);
    lo = bpack(__float2bfloat16_rn(a - __bfloat162float(ha)),
               __float2bfloat16_rn(b - __bfloat162float(hb)));
    return bpack(ha, hb);
}
__device__ __forceinline__ uint32_t f2tf32(float x) {
    uint32_t u;
    asm("cvt.rna.tf32.f32 %0, %1;" : "=r"(u) : "f"(x));
    return u;
}

// ===========================================================================
// Balanced projections (tf32 m16n8k8), grid x = 9:
//   x in [0,8): V tile  C[row0:+128, x*128:+128] = A @ Wv^T
//   x == 8:    K|Q tile (cols 0-63 -> K, 64-127 -> Q*0.125)
// One 128x128 output per CTA, one accumulator set, uniform work.
// ===========================================================================
#define VP_SMEM (2 * 128 * 36 * 4)      // 36864

__global__ __launch_bounds__(256, 1) void proj_tf32(
    const float* __restrict__ A, const float* __restrict__ W,
    const float* __restrict__ Wk, const float* __restrict__ Wq,
    __nv_bfloat16* __restrict__ Vh, __nv_bfloat16* __restrict__ Vl,
    __nv_bfloat16* __restrict__ Kh, __nv_bfloat16* __restrict__ Kl,
    __nv_bfloat16* __restrict__ Qh, __nv_bfloat16* __restrict__ Ql)
{
    extern __shared__ char sm[];
    uint32_t* As = (uint32_t*)sm;            // [128][36]
    uint32_t* Bs = As + 128*36;              // [128][36]
    const int tid = threadIdx.x, wid = tid >> 5, lane = tid & 31;
    const int g = lane >> 2, t = lane & 3;
    const int row0 = blockIdx.y * 128;
    const bool isv = (blockIdx.x < 8);
    const int col0 = blockIdx.x * 128;
    const int m0 = (wid & 3) * 32, n0 = (wid >> 2) * 64;

    float o[16][4];
    #pragma unroll
    for (int i = 0; i < 16; i++)
        #pragma unroll
        for (int j = 0; j < 4; j++) o[i][j] = 0.f;

    const int lr = tid >> 1, lc0 = (tid & 1) * 16;
    const float* arow = A + (size_t)(row0 + lr) * EMB + lc0;
    const float* brow = isv
        ? W + (size_t)(col0 + lr) * EMB + lc0
        : (lr < 64 ? Wk + (size_t)lr * EMB : Wq + (size_t)(lr - 64) * EMB) + lc0;

    for (int kc = 0; kc < EMB / 32; kc++) {
        #pragma unroll
        for (int j = 0; j < 4; j++) {
            float4 va = *(const float4*)(arow + kc * 32 + j * 4);
            As[lr*36 + lc0 + j*4 + 0] = f2tf32(va.x);
            As[lr*36 + lc0 + j*4 + 1] = f2tf32(va.y);
            As[lr*36 + lc0 + j*4 + 2] = f2tf32(va.z);
            As[lr*36 + lc0 + j*4 + 3] = f2tf32(va.w);
            float4 vb = *(const float4*)(brow + kc * 32 + j * 4);
            Bs[lr*36 + lc0 + j*4 + 0] = f2tf32(vb.x);
            Bs[lr*36 + lc0 + j*4 + 1] = f2tf32(vb.y);
            Bs[lr*36 + lc0 + j*4 + 2] = f2tf32(vb.z);
            Bs[lr*36 + lc0 + j*4 + 3] = f2tf32(vb.w);
        }
        __syncthreads();
        #pragma unroll
        for (int ks = 0; ks < 4; ks++) {
            uint32_t a[2][4];
            #pragma unroll
            for (int mt = 0; mt < 2; mt++) {
                const int r = m0 + mt*16;
                a[mt][0] = As[(r + g)*36     + ks*8 + t];
                a[mt][1] = As[(r + 8 + g)*36 + ks*8 + t];
                a[mt][2] = As[(r + g)*36     + ks*8 + t + 4];
                a[mt][3] = As[(r + 8 + g)*36 + ks*8 + t + 4];
            }
            #pragma unroll
            for (int nt = 0; nt < 8; nt++) {
                uint32_t b0 = Bs[(n0 + nt*8 + g)*36 + ks*8 + t];
                uint32_t b1 = Bs[(n0 + nt*8 + g)*36 + ks*8 + t + 4];
                #pragma unroll
                for (int mt = 0; mt < 2; mt++)
                    MMA_TF32(o[mt*8 + nt], a[mt], b0, b1);
            }
        }
        __syncthreads();
    }

    if (isv) {
        #pragma unroll
        for (int mt = 0; mt < 2; mt++)
            #pragma unroll
            for (int nt = 0; nt < 8; nt++) {
                const int r0 = row0 + m0 + mt*16 + g;
                const int c  = col0 + n0 + nt*8 + 2*t;
                uint32_t lo0, lo1;
                uint32_t hi0 = packsplit2(o[mt*8+nt][0], o[mt*8+nt][1], lo0);
                uint32_t hi1 = packsplit2(o[mt*8+nt][2], o[mt*8+nt][3], lo1);
                *(uint32_t*)(Vh + (size_t)r0 * EMB + c)       = hi0;
                *(uint32_t*)(Vl + (size_t)r0 * EMB + c)       = lo0;
                *(uint32_t*)(Vh + (size_t)(r0 + 8) * EMB + c) = hi1;
                *(uint32_t*)(Vl + (size_t)(r0 + 8) * EMB + c) = lo1;
            }
    } else {
        // n0==0 -> K, n0==64 -> Q (scaled by softmax 1/sqrt(64))
        const bool isq = (n0 != 0);
        const float scl = isq ? 0.125f : 1.0f;
        __nv_bfloat16* Ch = isq ? Qh : Kh;
        __nv_bfloat16* Cl = isq ? Ql : Kl;
        #pragma unroll
        for (int mt = 0; mt < 2; mt++)
            #pragma unroll
            for (int nt = 0; nt < 8; nt++) {
                const int r0 = row0 + m0 + mt*16 + g;
                const int c  = nt*8 + 2*t;
                uint32_t lo0, lo1;
                uint32_t hi0 = packsplit2(o[mt*8+nt][0]*scl, o[mt*8+nt][1]*scl, lo0);
                uint32_t hi1 = packsplit2(o[mt*8+nt][2]*scl, o[mt*8+nt][3]*scl, lo1);
                *(uint32_t*)(Ch + (size_t)r0 * HEADSZ + c)       = hi0;
                *(uint32_t*)(Cl + (size_t)r0 * HEADSZ + c)       = lo0;
                *(uint32_t*)(Ch + (size_t)(r0 + 8) * HEADSZ + c) = hi1;
                *(uint32_t*)(Cl + (size_t)(r0 + 8) * HEADSZ + c) = lo1;
            }
    }
}

// ===========================================================================
// Flash attention, register-resident P. 256 threads, CTA = 128 q x 128 dims.
// Q pre-scaled by 0.125 at projection; interior tiles skip causal compares.
// ===========================================================================
#define AQ_H   0                          // Q hi: 128 x 144B
#define AQ_L   18432                      // Q lo
#define AK     36864                      // K stages: 3 x 18432 (lo at +9216)
#define AV     92160                      // V stages: 3 x 34816 (lo at +17408)
#define A_SMEM 196608

__global__ __launch_bounds__(256, 1) void attn_reg(
    const __nv_bfloat16* __restrict__ Qh, const __nv_bfloat16* __restrict__ Ql,
    const __nv_bfloat16* __restrict__ Kh, const __nv_bfloat16* __restrict__ Kl,
    const __nv_bfloat16* __restrict__ Vh, const __nv_bfloat16* __restrict__ Vl,
    float* __restrict__ out)
{
    extern __shared__ char sm[];
    const uint32_t smb = smem_u32(sm);
    const int tid = threadIdx.x, wid = tid >> 5, lane = tid & 31;
    const int g = lane >> 2, t = lane & 3;
    const int qt = (SEQ/128 - 1) - blockIdx.y;
    const int q0 = qt * 128;
    const int d0 = blockIdx.x * 128;
    const int nkt = 2*qt + 2;
    const size_t tok0 = (size_t)blockIdx.z * SEQ;

    auto load_kv = [&](int kt, int stg) {
        const int row = tid >> 2;
        const size_t key = tok0 + kt*64 + row;
        {   const int c = (tid & 3) * 32;
            const char* gh = (const char*)(Kh + key * HEADSZ) + c;
            const char* gl = (const char*)(Kl + key * HEADSZ) + c;
            const uint32_t dk = smb + AK + stg*18432 + row*144 + c;
            CPA16(dk,          gh);
            CPA16(dk + 16,     gh + 16);
            CPA16(dk + 9216,   gl);
            CPA16(dk + 9216 + 16, gl + 16);
        }
        {   const int c = (tid & 3) * 64;
            const char* gh = (const char*)(Vh + key * EMB + d0) + c;
            const char* gl = (const char*)(Vl + key * EMB + d0) + c;
            const uint32_t dv = smb + AV + stg*34816 + row*272 + c;
            #pragma unroll
            for (int j = 0; j < 4; j++) {
                CPA16(dv + j*16,         gh + j*16);
                CPA16(dv + 17408 + j*16, gl + j*16);
            }
        }
    };

    // prologue: Q + KV0 (G0), KV1 (G1)
    {
        const int row = tid >> 1, c = (tid & 1) * 64;
        const char* gh = (const char*)(Qh + (tok0 + q0 + row) * HEADSZ) + c;
        const char* gl = (const char*)(Ql + (tok0 + q0 + row) * HEADSZ) + c;
        const uint32_t dq = smb + AQ_H + row*144 + c;
        #pragma unroll
        for (int j = 0; j < 4; j++) {
            CPA16(dq + j*16,                 gh + j*16);
            CPA16(dq + (AQ_L - AQ_H) + j*16, gl + j*16);
        }
    }
    load_kv(0, 0);
    CPA_COMMIT();
    load_kv(1, 1);
    CPA_COMMIT();

    uint32_t qah[4][4], qal[4][4];
    float o[16][4];
    #pragma unroll
    for (int i = 0; i < 16; i++)
        #pragma unroll
        for (int j = 0; j < 4; j++) o[i][j] = 0.f;
    float m0 = -1e30f, m1 = -1e30f, l0 = 0.f, l1 = 0.f;
    const int qbase = q0 + wid*16;
    const int qr0 = qbase + g, qr1 = qr0 + 8;

    for (int kt = 0; kt < nkt; kt++) {
        const int stg = kt % 3;
        if (kt + 1 < nkt) { CPA_WAIT(1); } else { CPA_WAIT(0); }
        __syncthreads();
        if (kt == 0) {
            #pragma unroll
            for (int ks = 0; ks < 4; ks++) {
                LDMX4(qah[ks], a_addr(smb + AQ_H, wid*16, ks*32, lane, 144));
                LDMX4(qal[ks], a_addr(smb + AQ_L, wid*16, ks*32, lane, 144));
            }
        }
        if (kt + 2 < nkt) {
            load_kv(kt + 2, (kt + 2) % 3);
            CPA_COMMIT();
        }

        // ---- S = Q @ K^T (pre-scaled) ----
        float s[8][4];
        #pragma unroll
        for (int i = 0; i < 8; i++)
            #pragma unroll
            for (int j = 0; j < 4; j++) s[i][j] = 0.f;
        const uint32_t kb = smb + AK + stg*18432;
        #pragma unroll
        for (int ks = 0; ks < 4; ks++) {
            #pragma unroll
            for (int ntp = 0; ntp < 4; ntp++) {
                uint32_t bh4[4], bl4[4];
                const uint32_t ka = kb +
                    (uint32_t)(ntp*16 + (lane & 7) + ((lane >> 4) << 3)) * 144
                    + ks*32 + (((lane >> 3) & 1) << 4);
                LDMX4(bh4, ka);
                LDMX4(bl4, ka + 9216);
                MMA3(s[2*ntp],     qah[ks], qal[ks], bh4,     bl4);
                MMA3(s[2*ntp + 1], qah[ks], qal[ks], bh4 + 2, bl4 + 2);
            }
        }

        // ---- mask (interior tiles skip compares) + in-warp online softmax ----
        float mx0 = -1e30f, mx1 = -1e30f;
        if (kt*64 + 63 <= qbase) {                 // fully unmasked tile
            #pragma unroll
            for (int nt = 0; nt < 8; nt++) {
                mx0 = fmaxf(mx0, fmaxf(s[nt][0], s[nt][1]));
                mx1 = fmaxf(mx1, fmaxf(s[nt][2], s[nt][3]));
            }
        } else {
            #pragma unroll
            for (int nt = 0; nt < 8; nt++) {
                const int c = kt*64 + nt*8 + 2*t;
                s[nt][0] = (c     <= qr0) ? s[nt][0] : -1e30f;
                s[nt][1] = (c + 1 <= qr0) ? s[nt][1] : -1e30f;
                s[nt][2] = (c     <= qr1) ? s[nt][2] : -1e30f;
                s[nt][3] = (c + 1 <= qr1) ? s[nt][3] : -1e30f;
                mx0 = fmaxf(mx0, fmaxf(s[nt][0], s[nt][1]));
                mx1 = fmaxf(mx1, fmaxf(s[nt][2], s[nt][3]));
            }
        }
        mx0 = fmaxf(mx0, __shfl_xor_sync(0xffffffffu, mx0, 1));
        mx0 = fmaxf(mx0, __shfl_xor_sync(0xffffffffu, mx0, 2));
        mx1 = fmaxf(mx1, __shfl_xor_sync(0xffffffffu, mx1, 1));
        mx1 = fmaxf(mx1, __shfl_xor_sync(0xffffffffu, mx1, 2));
        const float mn0 = fmaxf(m0, mx0), mn1 = fmaxf(m1, mx1);
        const float sc0 = __expf(m0 - mn0), sc1 = __expf(m1 - mn1);
        float sum0 = 0.f, sum1 = 0.f;
        #pragma unroll
        for (int nt = 0; nt < 8; nt++) {
            s[nt][0] = __expf(s[nt][0] - mn0);
            s[nt][1] = __expf(s[nt][1] - mn0);
            s[nt][2] = __expf(s[nt][2] - mn1);
            s[nt][3] = __expf(s[nt][3] - mn1);
            sum0 += s[nt][0] + s[nt][1];
            sum1 += s[nt][2] + s[nt][3];
        }
        sum0 += __shfl_xor_sync(0xffffffffu, sum0, 1);
        sum0 += __shfl_xor_sync(0xffffffffu, sum0, 2);
        sum1 += __shfl_xor_sync(0xffffffffu, sum1, 1);
        sum1 += __shfl_xor_sync(0xffffffffu, sum1, 2);
        l0 = l0*sc0 + sum0; l1 = l1*sc1 + sum1;
        m0 = mn0; m1 = mn1;

        // ---- pack P A-fragments (hi/lo) ----
        uint32_t ph[4][4], pl[4][4];
        #pragma unroll
        for (int ks = 0; ks < 4; ks++) {
            ph[ks][0] = packsplit2(s[2*ks][0],     s[2*ks][1],     pl[ks][0]);
            ph[ks][1] = packsplit2(s[2*ks][2],     s[2*ks][3],     pl[ks][1]);
            ph[ks][2] = packsplit2(s[2*ks + 1][0], s[2*ks + 1][1], pl[ks][2]);
            ph[ks][3] = packsplit2(s[2*ks + 1][2], s[2*ks + 1][3], pl[ks][3]);
        }

        // ---- rescale O, O += P @ V ----
        #pragma unroll
        for (int nt = 0; nt < 16; nt++) {
            o[nt][0] *= sc0; o[nt][1] *= sc0;
            o[nt][2] *= sc1; o[nt][3] *= sc1;
        }
        const uint32_t vb = smb + AV + stg*34816;
        #pragma unroll
        for (int ks = 0; ks < 4; ks++) {
            #pragma unroll
            for (int ntp = 0; ntp < 8; ntp++) {
                uint32_t vh4[4], vl4[4];
                const uint32_t va = vb +
                    (uint32_t)(ks*16 + (lane & 7) + (((lane >> 3) & 1) << 3)) * 272
                    + (ntp*16 + ((lane >> 4) << 3)) * 2;
                LDMX4T(vh4, va);
                LDMX4T(vl4, va + 17408);
                MMA3(o[2*ntp],     ph[ks], pl[ks], vh4,     vl4);
                MMA3(o[2*ntp + 1], ph[ks], pl[ks], vh4 + 2, vl4 + 2);
            }
        }
    }

    // ---- normalize + store ----
    const float i0 = 1.f / l0, i1 = 1.f / l1;
    const int r0 = wid*16 + g;
    #pragma unroll
    for (int nt = 0; nt < 16; nt++) {
        const int c = d0 + nt*8 + 2*t;
        float2 v0 = make_float2(o[nt][0]*i0, o[nt][1]*i0);
        float2 v1 = make_float2(o[nt][2]*i1, o[nt][3]*i1);
        *(float2*)(out + (tok0 + q0 + r0)     * EMB + c) = v0;
        *(float2*)(out + (tok0 + q0 + r0 + 8) * EMB + c) = v1;
    }
}

// ===========================================================================
extern "C" void kernel_launch(void* const* d_in, const int* in_sizes, int n_in,
                              void* d_out, int out_size)
{
    const float* x  = (const float*)d_in[0];
    const float* Wk = (const float*)d_in[1];
    const float* Wq = (const float*)d_in[2];
    const float* Wv = (const float*)d_in[3];
    float* out = (float*)d_out;

    __nv_bfloat16 *Qh, *Ql, *Kh, *Kl, *Vh, *Vl;
    cudaGetSymbolAddress((void**)&Qh, g_Qh);
    cudaGetSymbolAddress((void**)&Ql, g_Ql);
    cudaGetSymbolAddress((void**)&Kh, g_Kh);
    cudaGetSymbolAddress((void**)&Kl, g_Kl);
    cudaGetSymbolAddress((void**)&Vh, g_Vh);
    cudaGetSymbolAddress((void**)&Vl, g_Vl);

    cudaFuncSetAttribute(proj_tf32, cudaFuncAttributeMaxDynamicSharedMemorySize, VP_SMEM);
    cudaFuncSetAttribute(attn_reg,  cudaFuncAttributeMaxDynamicSharedMemorySize, A_SMEM);

    // Balanced V + K|Q projections (tf32 tensor): 9 columns x 128 row-tiles
    proj_tf32<<<dim3(9, BT/128), 256, VP_SMEM>>>(
        x, Wv, Wk, Wq, Vh, Vl, Kh, Kl, Qh, Ql);

    // Flash attention, register P
    attn_reg<<<dim3(EMB/128, SEQ/128, BATCH), 256, A_SMEM>>>(
        Qh, Ql, Kh, Kl, Vh, Vl, out);
}

// round 11
// speedup vs baseline: 1.1028x; 1.0384x over previous
#include <cuda_runtime.h>
#include <cuda_bf16.h>
#include <cstdint>

#define HEADSZ 64
#define EMB    1024
#define BATCH  4
#define SEQ    4096
#define BT     (BATCH*SEQ)

// Scratch (allocation-free)
__device__ __nv_bfloat16 g_Qh[(size_t)BT*HEADSZ];
__device__ __nv_bfloat16 g_Ql[(size_t)BT*HEADSZ];
__device__ __nv_bfloat16 g_Kh[(size_t)BT*HEADSZ];
__device__ __nv_bfloat16 g_Kl[(size_t)BT*HEADSZ];
__device__ __nv_bfloat16 g_Vh[(size_t)BT*EMB];
__device__ __nv_bfloat16 g_Vl[(size_t)BT*EMB];

// ===========================================================================
// helpers
// ===========================================================================
__device__ __forceinline__ uint32_t smem_u32(const void* p) {
    uint32_t a;
    asm("{ .reg .u64 t; cvta.to.shared.u64 t, %1; cvt.u32.u64 %0, t; }"
        : "=r"(a) : "l"(p));
    return a;
}

#define LDMX4(r, a) \
    asm volatile("ldmatrix.sync.aligned.m8n8.x4.shared.b16 {%0,%1,%2,%3}, [%4];" \
        : "=r"((r)[0]), "=r"((r)[1]), "=r"((r)[2]), "=r"((r)[3]) : "r"(a))
#define LDMX4T(r, a) \
    asm volatile("ldmatrix.sync.aligned.m8n8.x4.trans.shared.b16 {%0,%1,%2,%3}, [%4];" \
        : "=r"((r)[0]), "=r"((r)[1]), "=r"((r)[2]), "=r"((r)[3]) : "r"(a))

#define MMA_BF16(d, a, b) \
    asm volatile("mma.sync.aligned.m16n8k16.row.col.f32.bf16.bf16.f32 " \
        "{%0,%1,%2,%3}, {%4,%5,%6,%7}, {%8,%9}, {%0,%1,%2,%3};" \
        : "+f"((d)[0]), "+f"((d)[1]), "+f"((d)[2]), "+f"((d)[3]) \
        : "r"((a)[0]), "r"((a)[1]), "r"((a)[2]), "r"((a)[3]), \
          "r"((b)[0]), "r"((b)[1]))

#define MMA3(d, ah, al, bh, bl) do { \
    MMA_BF16(d, ah, bh); MMA_BF16(d, ah, bl); MMA_BF16(d, al, bh); } while (0)

#define MMA_TF32(d, a, b0, b1) \
    asm volatile("mma.sync.aligned.m16n8k8.row.col.f32.tf32.tf32.f32 " \
        "{%0,%1,%2,%3}, {%4,%5,%6,%7}, {%8,%9}, {%0,%1,%2,%3};" \
        : "+f"((d)[0]), "+f"((d)[1]), "+f"((d)[2]), "+f"((d)[3]) \
        : "r"((a)[0]), "r"((a)[1]), "r"((a)[2]), "r"((a)[3]), \
          "r"(b0), "r"(b1))

#define CPA16(dst, src) \
    asm volatile("cp.async.cg.shared.global [%0], [%1], 16;" :: "r"(dst), "l"(src))
#define CPA_COMMIT() asm volatile("cp.async.commit_group;" ::: "memory")
#define CPA_WAIT(n)  asm volatile("cp.async.wait_group %0;" :: "n"(n) : "memory")

__device__ __forceinline__ uint32_t a_addr(uint32_t base, int row, int kbyte,
                                           int lane, int strideB) {
    return base + (uint32_t)(row + (lane & 15)) * strideB + kbyte +
           ((lane >> 4) << 4);
}

__device__ __forceinline__ uint32_t bpack(__nv_bfloat16 a, __nv_bfloat16 b) {
    return ((uint32_t)__bfloat16_as_ushort(b) << 16) |
           (uint32_t)__bfloat16_as_ushort(a);
}
__device__ __forceinline__ uint32_t packsplit2(float a, float b, uint32_t& lo) {
    __nv_bfloat16 ha = __float2bfloat16_rn(a), hb = __float2bfloat16_rn(b);
    lo = bpack(__float2bfloat16_rn(a - __bfloat162float(ha)),
               __float2bfloat16_rn(b - __bfloat162float(hb)));
    return bpack(ha, hb);
}
__device__ __forceinline__ uint32_t f2tf32(float x) {
    uint32_t u;
    asm("cvt.rna.tf32.f32 %0, %1;" : "=r"(u) : "f"(x));
    return u;
}

// ===========================================================================
// Balanced projections (tf32 m16n8k8), grid x = 9:
//   x in [0,8): V tile  C[row0:+128, x*128:+128] = A @ Wv^T
//   x == 8:    K|Q tile (cols 0-63 -> K, 64-127 -> Q*0.125)
// 3-stage cp.async pipeline of RAW fp32 tiles (A 128x32, B 128x32 per stage,
// 36-word padded rows); tf32 conversion at fragment fetch (same cvt.rna).
// ===========================================================================
#define VP_ASZ   18432                       // 128 rows x 144B
#define VP_STAGE (2*VP_ASZ)                  // A + B = 36864
#define VP_SMEM  (3*VP_STAGE)                // 110592

__global__ __launch_bounds__(256, 1) void proj_tf32(
    const float* __restrict__ A, const float* __restrict__ W,
    const float* __restrict__ Wk, const float* __restrict__ Wq,
    __nv_bfloat16* __restrict__ Vh, __nv_bfloat16* __restrict__ Vl,
    __nv_bfloat16* __restrict__ Kh, __nv_bfloat16* __restrict__ Kl,
    __nv_bfloat16* __restrict__ Qh, __nv_bfloat16* __restrict__ Ql)
{
    extern __shared__ char sm[];
    const uint32_t smb = smem_u32(sm);
    const int tid = threadIdx.x, wid = tid >> 5, lane = tid & 31;
    const int g = lane >> 2, t = lane & 3;
    const int row0 = blockIdx.y * 128;
    const bool isv = (blockIdx.x < 8);
    const int col0 = blockIdx.x * 128;
    const int m0 = (wid & 3) * 32, n0 = (wid >> 2) * 64;

    const int lr = tid >> 1, half = tid & 1;       // row, 64B half
    const float* arow = A + (size_t)(row0 + lr) * EMB + half*16;
    const float* brow = (isv
        ? W + (size_t)(col0 + lr) * EMB
        : (lr < 64 ? Wk + (size_t)lr * EMB : Wq + (size_t)(lr - 64) * EMB))
        + half*16;

    auto load_tile = [&](int kc, int stg) {
        const uint32_t da = smb + stg*VP_STAGE + lr*144 + half*64;
        const char* ga = (const char*)(arow + kc*32);
        CPA16(da,      ga);
        CPA16(da + 16, ga + 16);
        CPA16(da + 32, ga + 32);
        CPA16(da + 48, ga + 48);
        const uint32_t db = da + VP_ASZ;
        const char* gb = (const char*)(brow + kc*32);
        CPA16(db,      gb);
        CPA16(db + 16, gb + 16);
        CPA16(db + 32, gb + 32);
        CPA16(db + 48, gb + 48);
    };

    load_tile(0, 0); CPA_COMMIT();
    load_tile(1, 1); CPA_COMMIT();

    float o[16][4];
    #pragma unroll
    for (int i = 0; i < 16; i++)
        #pragma unroll
        for (int j = 0; j < 4; j++) o[i][j] = 0.f;

    for (int kc = 0; kc < EMB/32; kc++) {
        const int stg = kc % 3;
        if (kc + 1 < EMB/32) { CPA_WAIT(1); } else { CPA_WAIT(0); }
        __syncthreads();
        if (kc + 2 < EMB/32) {
            load_tile(kc + 2, (kc + 2) % 3);
            CPA_COMMIT();
        }

        const float* As = (const float*)(sm + stg*VP_STAGE);
        const float* Bs = (const float*)(sm + stg*VP_STAGE + VP_ASZ);
        #pragma unroll
        for (int ks = 0; ks < 4; ks++) {
            uint32_t a[2][4];
            #pragma unroll
            for (int mt = 0; mt < 2; mt++) {
                const int r = m0 + mt*16;
                a[mt][0] = f2tf32(As[(r + g)*36     + ks*8 + t]);
                a[mt][1] = f2tf32(As[(r + 8 + g)*36 + ks*8 + t]);
                a[mt][2] = f2tf32(As[(r + g)*36     + ks*8 + t + 4]);
                a[mt][3] = f2tf32(As[(r + 8 + g)*36 + ks*8 + t + 4]);
            }
            #pragma unroll
            for (int nt = 0; nt < 8; nt++) {
                uint32_t b0 = f2tf32(Bs[(n0 + nt*8 + g)*36 + ks*8 + t]);
                uint32_t b1 = f2tf32(Bs[(n0 + nt*8 + g)*36 + ks*8 + t + 4]);
                #pragma unroll
                for (int mt = 0; mt < 2; mt++)
                    MMA_TF32(o[mt*8 + nt], a[mt], b0, b1);
            }
        }
    }

    if (isv) {
        #pragma unroll
        for (int mt = 0; mt < 2; mt++)
            #pragma unroll
            for (int nt = 0; nt < 8; nt++) {
                const int r0 = row0 + m0 + mt*16 + g;
                const int c  = col0 + n0 + nt*8 + 2*t;
                uint32_t lo0, lo1;
                uint32_t hi0 = packsplit2(o[mt*8+nt][0], o[mt*8+nt][1], lo0);
                uint32_t hi1 = packsplit2(o[mt*8+nt][2], o[mt*8+nt][3], lo1);
                *(uint32_t*)(Vh + (size_t)r0 * EMB + c)       = hi0;
                *(uint32_t*)(Vl + (size_t)r0 * EMB + c)       = lo0;
                *(uint32_t*)(Vh + (size_t)(r0 + 8) * EMB + c) = hi1;
                *(uint32_t*)(Vl + (size_t)(r0 + 8) * EMB + c) = lo1;
            }
    } else {
        const bool isq = (n0 != 0);
        const float scl = isq ? 0.125f : 1.0f;
        __nv_bfloat16* Ch = isq ? Qh : Kh;
        __nv_bfloat16* Cl = isq ? Ql : Kl;
        #pragma unroll
        for (int mt = 0; mt < 2; mt++)
            #pragma unroll
            for (int nt = 0; nt < 8; nt++) {
                const int r0 = row0 + m0 + mt*16 + g;
                const int c  = nt*8 + 2*t;
                uint32_t lo0, lo1;
                uint32_t hi0 = packsplit2(o[mt*8+nt][0]*scl, o[mt*8+nt][1]*scl, lo0);
                uint32_t hi1 = packsplit2(o[mt*8+nt][2]*scl, o[mt*8+nt][3]*scl, lo1);
                *(uint32_t*)(Ch + (size_t)r0 * HEADSZ + c)       = hi0;
                *(uint32_t*)(Cl + (size_t)r0 * HEADSZ + c)       = lo0;
                *(uint32_t*)(Ch + (size_t)(r0 + 8) * HEADSZ + c) = hi1;
                *(uint32_t*)(Cl + (size_t)(r0 + 8) * HEADSZ + c) = lo1;
            }
    }
}

// ===========================================================================
// Flash attention, register-resident P. 256 threads, CTA = 128 q x 128 dims.
// (unchanged from round 10 — 870 us, tensor 60.4%)
// ===========================================================================
#define AQ_H   0                          // Q hi: 128 x 144B
#define AQ_L   18432                      // Q lo
#define AK     36864                      // K stages: 3 x 18432 (lo at +9216)
#define AV     92160                      // V stages: 3 x 34816 (lo at +17408)
#define A_SMEM 196608

__global__ __launch_bounds__(256, 1) void attn_reg(
    const __nv_bfloat16* __restrict__ Qh, const __nv_bfloat16* __restrict__ Ql,
    const __nv_bfloat16* __restrict__ Kh, const __nv_bfloat16* __restrict__ Kl,
    const __nv_bfloat16* __restrict__ Vh, const __nv_bfloat16* __restrict__ Vl,
    float* __restrict__ out)
{
    extern __shared__ char sm[];
    const uint32_t smb = smem_u32(sm);
    const int tid = threadIdx.x, wid = tid >> 5, lane = tid & 31;
    const int g = lane >> 2, t = lane & 3;
    const int qt = (SEQ/128 - 1) - blockIdx.y;
    const int q0 = qt * 128;
    const int d0 = blockIdx.x * 128;
    const int nkt = 2*qt + 2;
    const size_t tok0 = (size_t)blockIdx.z * SEQ;

    auto load_kv = [&](int kt, int stg) {
        const int row = tid >> 2;
        const size_t key = tok0 + kt*64 + row;
        {   const int c = (tid & 3) * 32;
            const char* gh = (const char*)(Kh + key * HEADSZ) + c;
            const char* gl = (const char*)(Kl + key * HEADSZ) + c;
            const uint32_t dk = smb + AK + stg*18432 + row*144 + c;
            CPA16(dk,          gh);
            CPA16(dk + 16,     gh + 16);
            CPA16(dk + 9216,   gl);
            CPA16(dk + 9216 + 16, gl + 16);
        }
        {   const int c = (tid & 3) * 64;
            const char* gh = (const char*)(Vh + key * EMB + d0) + c;
            const char* gl = (const char*)(Vl + key * EMB + d0) + c;
            const uint32_t dv = smb + AV + stg*34816 + row*272 + c;
            #pragma unroll
            for (int j = 0; j < 4; j++) {
                CPA16(dv + j*16,         gh + j*16);
                CPA16(dv + 17408 + j*16, gl + j*16);
            }
        }
    };

    // prologue: Q + KV0 (G0), KV1 (G1)
    {
        const int row = tid >> 1, c = (tid & 1) * 64;
        const char* gh = (const char*)(Qh + (tok0 + q0 + row) * HEADSZ) + c;
        const char* gl = (const char*)(Ql + (tok0 + q0 + row) * HEADSZ) + c;
        const uint32_t dq = smb + AQ_H + row*144 + c;
        #pragma unroll
        for (int j = 0; j < 4; j++) {
            CPA16(dq + j*16,                 gh + j*16);
            CPA16(dq + (AQ_L - AQ_H) + j*16, gl + j*16);
        }
    }
    load_kv(0, 0);
    CPA_COMMIT();
    load_kv(1, 1);
    CPA_COMMIT();

    uint32_t qah[4][4], qal[4][4];
    float o[16][4];
    #pragma unroll
    for (int i = 0; i < 16; i++)
        #pragma unroll
        for (int j = 0; j < 4; j++) o[i][j] = 0.f;
    float m0 = -1e30f, m1 = -1e30f, l0 = 0.f, l1 = 0.f;
    const int qbase = q0 + wid*16;
    const int qr0 = qbase + g, qr1 = qr0 + 8;

    for (int kt = 0; kt < nkt; kt++) {
        const int stg = kt % 3;
        if (kt + 1 < nkt) { CPA_WAIT(1); } else { CPA_WAIT(0); }
        __syncthreads();
        if (kt == 0) {
            #pragma unroll
            for (int ks = 0; ks < 4; ks++) {
                LDMX4(qah[ks], a_addr(smb + AQ_H, wid*16, ks*32, lane, 144));
                LDMX4(qal[ks], a_addr(smb + AQ_L, wid*16, ks*32, lane, 144));
            }
        }
        if (kt + 2 < nkt) {
            load_kv(kt + 2, (kt + 2) % 3);
            CPA_COMMIT();
        }

        // ---- S = Q @ K^T (pre-scaled) ----
        float s[8][4];
        #pragma unroll
        for (int i = 0; i < 8; i++)
            #pragma unroll
            for (int j = 0; j < 4; j++) s[i][j] = 0.f;
        const uint32_t kb = smb + AK + stg*18432;
        #pragma unroll
        for (int ks = 0; ks < 4; ks++) {
            #pragma unroll
            for (int ntp = 0; ntp < 4; ntp++) {
                uint32_t bh4[4], bl4[4];
                const uint32_t ka = kb +
                    (uint32_t)(ntp*16 + (lane & 7) + ((lane >> 4) << 3)) * 144
                    + ks*32 + (((lane >> 3) & 1) << 4);
                LDMX4(bh4, ka);
                LDMX4(bl4, ka + 9216);
                MMA3(s[2*ntp],     qah[ks], qal[ks], bh4,     bl4);
                MMA3(s[2*ntp + 1], qah[ks], qal[ks], bh4 + 2, bl4 + 2);
            }
        }

        // ---- mask (interior tiles skip compares) + in-warp online softmax ----
        float mx0 = -1e30f, mx1 = -1e30f;
        if (kt*64 + 63 <= qbase) {
            #pragma unroll
            for (int nt = 0; nt < 8; nt++) {
                mx0 = fmaxf(mx0, fmaxf(s[nt][0], s[nt][1]));
                mx1 = fmaxf(mx1, fmaxf(s[nt][2], s[nt][3]));
            }
        } else {
            #pragma unroll
            for (int nt = 0; nt < 8; nt++) {
                const int c = kt*64 + nt*8 + 2*t;
                s[nt][0] = (c     <= qr0) ? s[nt][0] : -1e30f;
                s[nt][1] = (c + 1 <= qr0) ? s[nt][1] : -1e30f;
                s[nt][2] = (c     <= qr1) ? s[nt][2] : -1e30f;
                s[nt][3] = (c + 1 <= qr1) ? s[nt][3] : -1e30f;
                mx0 = fmaxf(mx0, fmaxf(s[nt][0], s[nt][1]));
                mx1 = fmaxf(mx1, fmaxf(s[nt][2], s[nt][3]));
            }
        }
        mx0 = fmaxf(mx0, __shfl_xor_sync(0xffffffffu, mx0, 1));
        mx0 = fmaxf(mx0, __shfl_xor_sync(0xffffffffu, mx0, 2));
        mx1 = fmaxf(mx1, __shfl_xor_sync(0xffffffffu, mx1, 1));
        mx1 = fmaxf(mx1, __shfl_xor_sync(0xffffffffu, mx1, 2));
        const float mn0 = fmaxf(m0, mx0), mn1 = fmaxf(m1, mx1);
        const float sc0 = __expf(m0 - mn0), sc1 = __expf(m1 - mn1);
        float sum0 = 0.f, sum1 = 0.f;
        #pragma unroll
        for (int nt = 0; nt < 8; nt++) {
            s[nt][0] = __expf(s[nt][0] - mn0);
            s[nt][1] = __expf(s[nt][1] - mn0);
            s[nt][2] = __expf(s[nt][2] - mn1);
            s[nt][3] = __expf(s[nt][3] - mn1);
            sum0 += s[nt][0] + s[nt][1];
            sum1 += s[nt][2] + s[nt][3];
        }
        sum0 += __shfl_xor_sync(0xffffffffu, sum0, 1);
        sum0 += __shfl_xor_sync(0xffffffffu, sum0, 2);
        sum1 += __shfl_xor_sync(0xffffffffu, sum1, 1);
        sum1 += __shfl_xor_sync(0xffffffffu, sum1, 2);
        l0 = l0*sc0 + sum0; l1 = l1*sc1 + sum1;
        m0 = mn0; m1 = mn1;

        // ---- pack P A-fragments (hi/lo) ----
        uint32_t ph[4][4], pl[4][4];
        #pragma unroll
        for (int ks = 0; ks < 4; ks++) {
            ph[ks][0] = packsplit2(s[2*ks][0],     s[2*ks][1],     pl[ks][0]);
            ph[ks][1] = packsplit2(s[2*ks][2],     s[2*ks][3],     pl[ks][1]);
            ph[ks][2] = packsplit2(s[2*ks + 1][0], s[2*ks + 1][1], pl[ks][2]);
            ph[ks][3] = packsplit2(s[2*ks + 1][2], s[2*ks + 1][3], pl[ks][3]);
        }

        // ---- rescale O, O += P @ V ----
        #pragma unroll
        for (int nt = 0; nt < 16; nt++) {
            o[nt][0] *= sc0; o[nt][1] *= sc0;
            o[nt][2] *= sc1; o[nt][3] *= sc1;
        }
        const uint32_t vb = smb + AV + stg*34816;
        #pragma unroll
        for (int ks = 0; ks < 4; ks++) {
            #pragma unroll
            for (int ntp = 0; ntp < 8; ntp++) {
                uint32_t vh4[4], vl4[4];
                const uint32_t va = vb +
                    (uint32_t)(ks*16 + (lane & 7) + (((lane >> 3) & 1) << 3)) * 272
                    + (ntp*16 + ((lane >> 4) << 3)) * 2;
                LDMX4T(vh4, va);
                LDMX4T(vl4, va + 17408);
                MMA3(o[2*ntp],     ph[ks], pl[ks], vh4,     vl4);
                MMA3(o[2*ntp + 1], ph[ks], pl[ks], vh4 + 2, vl4 + 2);
            }
        }
    }

    // ---- normalize + store ----
    const float i0 = 1.f / l0, i1 = 1.f / l1;
    const int r0 = wid*16 + g;
    #pragma unroll
    for (int nt = 0; nt < 16; nt++) {
        const int c = d0 + nt*8 + 2*t;
        float2 v0 = make_float2(o[nt][0]*i0, o[nt][1]*i0);
        float2 v1 = make_float2(o[nt][2]*i1, o[nt][3]*i1);
        *(float2*)(out + (tok0 + q0 + r0)     * EMB + c) = v0;
        *(float2*)(out + (tok0 + q0 + r0 + 8) * EMB + c) = v1;
    }
}

// ===========================================================================
extern "C" void kernel_launch(void* const* d_in, const int* in_sizes, int n_in,
                              void* d_out, int out_size)
{
    const float* x  = (const float*)d_in[0];
    const float* Wk = (const float*)d_in[1];
    const float* Wq = (const float*)d_in[2];
    const float* Wv = (const float*)d_in[3];
    float* out = (float*)d_out;

    __nv_bfloat16 *Qh, *Ql, *Kh, *Kl, *Vh, *Vl;
    cudaGetSymbolAddress((void**)&Qh, g_Qh);
    cudaGetSymbolAddress((void**)&Ql, g_Ql);
    cudaGetSymbolAddress((void**)&Kh, g_Kh);
    cudaGetSymbolAddress((void**)&Kl, g_Kl);
    cudaGetSymbolAddress((void**)&Vh, g_Vh);
    cudaGetSymbolAddress((void**)&Vl, g_Vl);

    cudaFuncSetAttribute(proj_tf32, cudaFuncAttributeMaxDynamicSharedMemorySize, VP_SMEM);
    cudaFuncSetAttribute(attn_reg,  cudaFuncAttributeMaxDynamicSharedMemorySize, A_SMEM);

    // Balanced V + K|Q projections (tf32 tensor), 3-stage cp.async pipeline
    proj_tf32<<<dim3(9, BT/128), 256, VP_SMEM>>>(
        x, Wv, Wk, Wq, Vh, Vl, Kh, Kl, Qh, Ql);

    // Flash attention, register P
    attn_reg<<<dim3(EMB/128, SEQ/128, BATCH), 256, A_SMEM>>>(
        Qh, Ql, Kh, Kl, Vh, Vl, out);
}

// round 15
// speedup vs baseline: 1.1571x; 1.0493x over previous
#include <cuda_runtime.h>
#include <cuda_bf16.h>
#include <cstdint>

#define HEADSZ 64
#define EMB    1024
#define BATCH  4
#define SEQ    4096
#define BT     (BATCH*SEQ)

// Scratch (allocation-free)
__device__ __nv_bfloat16 g_Qh[(size_t)BT*HEADSZ];
__device__ __nv_bfloat16 g_Ql[(size_t)BT*HEADSZ];
__device__ __nv_bfloat16 g_Kh[(size_t)BT*HEADSZ];
__device__ __nv_bfloat16 g_Kl[(size_t)BT*HEADSZ];
__device__ __nv_bfloat16 g_Vh[(size_t)BT*EMB];
__device__ __nv_bfloat16 g_Vl[(size_t)BT*EMB];

// ===========================================================================
// helpers
// ===========================================================================
__device__ __forceinline__ uint32_t smem_u32(const void* p) {
    uint32_t a;
    asm("{ .reg .u64 t; cvta.to.shared.u64 t, %1; cvt.u32.u64 %0, t; }"
        : "=r"(a) : "l"(p));
    return a;
}

#define LDMX4(r, a) \
    asm volatile("ldmatrix.sync.aligned.m8n8.x4.shared.b16 {%0,%1,%2,%3}, [%4];" \
        : "=r"((r)[0]), "=r"((r)[1]), "=r"((r)[2]), "=r"((r)[3]) : "r"(a))
#define LDMX4T(r, a) \
    asm volatile("ldmatrix.sync.aligned.m8n8.x4.trans.shared.b16 {%0,%1,%2,%3}, [%4];" \
        : "=r"((r)[0]), "=r"((r)[1]), "=r"((r)[2]), "=r"((r)[3]) : "r"(a))

#define MMA_BF16(d, a, b) \
    asm volatile("mma.sync.aligned.m16n8k16.row.col.f32.bf16.bf16.f32 " \
        "{%0,%1,%2,%3}, {%4,%5,%6,%7}, {%8,%9}, {%0,%1,%2,%3};" \
        : "+f"((d)[0]), "+f"((d)[1]), "+f"((d)[2]), "+f"((d)[3]) \
        : "r"((a)[0]), "r"((a)[1]), "r"((a)[2]), "r"((a)[3]), \
          "r"((b)[0]), "r"((b)[1]))

#define MMA3(d, ah, al, bh, bl) do { \
    MMA_BF16(d, ah, bh); MMA_BF16(d, ah, bl); MMA_BF16(d, al, bh); } while (0)

#define MMA_TF32(d, a, b0, b1) \
    asm volatile("mma.sync.aligned.m16n8k8.row.col.f32.tf32.tf32.f32 " \
        "{%0,%1,%2,%3}, {%4,%5,%6,%7}, {%8,%9}, {%0,%1,%2,%3};" \
        : "+f"((d)[0]), "+f"((d)[1]), "+f"((d)[2]), "+f"((d)[3]) \
        : "r"((a)[0]), "r"((a)[1]), "r"((a)[2]), "r"((a)[3]), \
          "r"(b0), "r"(b1))

#define CPA16(dst, src) \
    asm volatile("cp.async.cg.shared.global [%0], [%1], 16;" :: "r"(dst), "l"(src))
#define CPA_COMMIT() asm volatile("cp.async.commit_group;" ::: "memory")
#define CPA_WAIT(n)  asm volatile("cp.async.wait_group %0;" :: "n"(n) : "memory")

__device__ __forceinline__ uint32_t a_addr(uint32_t base, int row, int kbyte,
                                           int lane, int strideB) {
    return base + (uint32_t)(row + (lane & 15)) * strideB + kbyte +
           ((lane >> 4) << 4);
}

__device__ __forceinline__ uint32_t bpack(__nv_bfloat16 a, __nv_bfloat16 b) {
    return ((uint32_t)__bfloat16_as_ushort(b) << 16) |
           (uint32_t)__bfloat16_as_ushort(a);
}
__device__ __forceinline__ uint32_t packsplit2(float a, float b, uint32_t& lo) {
    __nv_bfloat16 ha = __float2bfloat16_rn(a), hb = __float2bfloat16_rn(b);
    lo = bpack(__float2bfloat16_rn(a - __bfloat162float(ha)),
               __float2bfloat16_rn(b - __bfloat162float(hb)));
    return bpack(ha, hb);
}
__device__ __forceinline__ uint32_t f2tf32(float x) {
    uint32_t u;
    asm("cvt.rna.tf32.f32 %0, %1;" : "=r"(u) : "f"(x));
    return u;
}

// ===========================================================================
// Balanced projections (tf32 m16n8k8), grid x = 9:
//   x in [0,8): V tile  C[row0:+128, x*128:+128] = A @ Wv^T
//   x == 8:    K|Q tile (cols 0-63 -> K, 64-127 -> Q*0.125)
// 2-stage cp.async pipeline (distance 1) of RAW fp32 tiles, 2 CTAs/SM.
// tf32 conversion at fragment fetch (same cvt.rna -> identical arithmetic).
// ===========================================================================
#define VP_ASZ   18432                       // 128 rows x 144B
#define VP_STAGE (2*VP_ASZ)                  // A + B = 36864
#define VP_SMEM  (2*VP_STAGE)                // 73728 -> 2 CTAs/SM

__global__ __launch_bounds__(256, 2) void proj_tf32(
    const float* __restrict__ A, const float* __restrict__ W,
    const float* __restrict__ Wk, const float* __restrict__ Wq,
    __nv_bfloat16* __restrict__ Vh, __nv_bfloat16* __restrict__ Vl,
    __nv_bfloat16* __restrict__ Kh, __nv_bfloat16* __restrict__ Kl,
    __nv_bfloat16* __restrict__ Qh, __nv_bfloat16* __restrict__ Ql)
{
    extern __shared__ char sm[];
    const uint32_t smb = smem_u32(sm);
    const int tid = threadIdx.x, wid = tid >> 5, lane = tid & 31;
    const int g = lane >> 2, t = lane & 3;
    const int row0 = blockIdx.y * 128;
    const bool isv = (blockIdx.x < 8);
    const int col0 = blockIdx.x * 128;
    const int m0 = (wid & 3) * 32, n0 = (wid >> 2) * 64;

    const int lr = tid >> 1, half = tid & 1;       // row, 64B half
    const float* arow = A + (size_t)(row0 + lr) * EMB + half*16;
    const float* brow = (isv
        ? W + (size_t)(col0 + lr) * EMB
        : (lr < 64 ? Wk + (size_t)lr * EMB : Wq + (size_t)(lr - 64) * EMB))
        + half*16;

    auto load_tile = [&](int kc, int stg) {
        const uint32_t da = smb + stg*VP_STAGE + lr*144 + half*64;
        const char* ga = (const char*)(arow + kc*32);
        CPA16(da,      ga);
        CPA16(da + 16, ga + 16);
        CPA16(da + 32, ga + 32);
        CPA16(da + 48, ga + 48);
        const uint32_t db = da + VP_ASZ;
        const char* gb = (const char*)(brow + kc*32);
        CPA16(db,      gb);
        CPA16(db + 16, gb + 16);
        CPA16(db + 32, gb + 32);
        CPA16(db + 48, gb + 48);
    };

    load_tile(0, 0); CPA_COMMIT();

    float o[16][4];
    #pragma unroll
    for (int i = 0; i < 16; i++)
        #pragma unroll
        for (int j = 0; j < 4; j++) o[i][j] = 0.f;

    for (int kc = 0; kc < EMB/32; kc++) {
        const int stg = kc & 1;
        CPA_WAIT(0);                 // tile kc resident
        __syncthreads();             // all warps done with stage stg^1
        if (kc + 1 < EMB/32) {
            load_tile(kc + 1, stg ^ 1);
            CPA_COMMIT();            // overlaps with compute below
        }

        const float* As = (const float*)(sm + stg*VP_STAGE);
        const float* Bs = (const float*)(sm + stg*VP_STAGE + VP_ASZ);
        #pragma unroll
        for (int ks = 0; ks < 4; ks++) {
            uint32_t a[2][4];
            #pragma unroll
            for (int mt = 0; mt < 2; mt++) {
                const int r = m0 + mt*16;
                a[mt][0] = f2tf32(As[(r + g)*36     + ks*8 + t]);
                a[mt][1] = f2tf32(As[(r + 8 + g)*36 + ks*8 + t]);
                a[mt][2] = f2tf32(As[(r + g)*36     + ks*8 + t + 4]);
                a[mt][3] = f2tf32(As[(r + 8 + g)*36 + ks*8 + t + 4]);
            }
            #pragma unroll
            for (int nt = 0; nt < 8; nt++) {
                uint32_t b0 = f2tf32(Bs[(n0 + nt*8 + g)*36 + ks*8 + t]);
                uint32_t b1 = f2tf32(Bs[(n0 + nt*8 + g)*36 + ks*8 + t + 4]);
                #pragma unroll
                for (int mt = 0; mt < 2; mt++)
                    MMA_TF32(o[mt*8 + nt], a[mt], b0, b1);
            }
        }
    }

    if (isv) {
        #pragma unroll
        for (int mt = 0; mt < 2; mt++)
            #pragma unroll
            for (int nt = 0; nt < 8; nt++) {
                const int r0 = row0 + m0 + mt*16 + g;
                const int c  = col0 + n0 + nt*8 + 2*t;
                uint32_t lo0, lo1;
                uint32_t hi0 = packsplit2(o[mt*8+nt][0], o[mt*8+nt][1], lo0);
                uint32_t hi1 = packsplit2(o[mt*8+nt][2], o[mt*8+nt][3], lo1);
                *(uint32_t*)(Vh + (size_t)r0 * EMB + c)       = hi0;
                *(uint32_t*)(Vl + (size_t)r0 * EMB + c)       = lo0;
                *(uint32_t*)(Vh + (size_t)(r0 + 8) * EMB + c) = hi1;
                *(uint32_t*)(Vl + (size_t)(r0 + 8) * EMB + c) = lo1;
            }
    } else {
        const bool isq = (n0 != 0);
        const float scl = isq ? 0.125f : 1.0f;
        __nv_bfloat16* Ch = isq ? Qh : Kh;
        __nv_bfloat16* Cl = isq ? Ql : Kl;
        #pragma unroll
        for (int mt = 0; mt < 2; mt++)
            #pragma unroll
            for (int nt = 0; nt < 8; nt++) {
                const int r0 = row0 + m0 + mt*16 + g;
                const int c  = nt*8 + 2*t;
                uint32_t lo0, lo1;
                uint32_t hi0 = packsplit2(o[mt*8+nt][0]*scl, o[mt*8+nt][1]*scl, lo0);
                uint32_t hi1 = packsplit2(o[mt*8+nt][2]*scl, o[mt*8+nt][3]*scl, lo1);
                *(uint32_t*)(Ch + (size_t)r0 * HEADSZ + c)       = hi0;
                *(uint32_t*)(Cl + (size_t)r0 * HEADSZ + c)       = lo0;
                *(uint32_t*)(Ch + (size_t)(r0 + 8) * HEADSZ + c) = hi1;
                *(uint32_t*)(Cl + (size_t)(r0 + 8) * HEADSZ + c) = lo1;
            }
    }
}

// ===========================================================================
// Flash attention, register-resident P. 256 threads, CTA = 128 q x 128 dims.
// (unchanged — 869.6 us, tensor 60.3%)
// ===========================================================================
#define AQ_H   0                          // Q hi: 128 x 144B
#define AQ_L   18432                      // Q lo
#define AK     36864                      // K stages: 3 x 18432 (lo at +9216)
#define AV     92160                      // V stages: 3 x 34816 (lo at +17408)
#define A_SMEM 196608

__global__ __launch_bounds__(256, 1) void attn_reg(
    const __nv_bfloat16* __restrict__ Qh, const __nv_bfloat16* __restrict__ Ql,
    const __nv_bfloat16* __restrict__ Kh, const __nv_bfloat16* __restrict__ Kl,
    const __nv_bfloat16* __restrict__ Vh, const __nv_bfloat16* __restrict__ Vl,
    float* __restrict__ out)
{
    extern __shared__ char sm[];
    const uint32_t smb = smem_u32(sm);
    const int tid = threadIdx.x, wid = tid >> 5, lane = tid & 31;
    const int g = lane >> 2, t = lane & 3;
    const int qt = (SEQ/128 - 1) - blockIdx.y;
    const int q0 = qt * 128;
    const int d0 = blockIdx.x * 128;
    const int nkt = 2*qt + 2;
    const size_t tok0 = (size_t)blockIdx.z * SEQ;

    auto load_kv = [&](int kt, int stg) {
        const int row = tid >> 2;
        const size_t key = tok0 + kt*64 + row;
        {   const int c = (tid & 3) * 32;
            const char* gh = (const char*)(Kh + key * HEADSZ) + c;
            const char* gl = (const char*)(Kl + key * HEADSZ) + c;
            const uint32_t dk = smb + AK + stg*18432 + row*144 + c;
            CPA16(dk,          gh);
            CPA16(dk + 16,     gh + 16);
            CPA16(dk + 9216,   gl);
            CPA16(dk + 9216 + 16, gl + 16);
        }
        {   const int c = (tid & 3) * 64;
            const char* gh = (const char*)(Vh + key * EMB + d0) + c;
            const char* gl = (const char*)(Vl + key * EMB + d0) + c;
            const uint32_t dv = smb + AV + stg*34816 + row*272 + c;
            #pragma unroll
            for (int j = 0; j < 4; j++) {
                CPA16(dv + j*16,         gh + j*16);
                CPA16(dv + 17408 + j*16, gl + j*16);
            }
        }
    };

    // prologue: Q + KV0 (G0), KV1 (G1)
    {
        const int row = tid >> 1, c = (tid & 1) * 64;
        const char* gh = (const char*)(Qh + (tok0 + q0 + row) * HEADSZ) + c;
        const char* gl = (const char*)(Ql + (tok0 + q0 + row) * HEADSZ) + c;
        const uint32_t dq = smb + AQ_H + row*144 + c;
        #pragma unroll
        for (int j = 0; j < 4; j++) {
            CPA16(dq + j*16,                 gh + j*16);
            CPA16(dq + (AQ_L - AQ_H) + j*16, gl + j*16);
        }
    }
    load_kv(0, 0);
    CPA_COMMIT();
    load_kv(1, 1);
    CPA_COMMIT();

    uint32_t qah[4][4], qal[4][4];
    float o[16][4];
    #pragma unroll
    for (int i = 0; i < 16; i++)
        #pragma unroll
        for (int j = 0; j < 4; j++) o[i][j] = 0.f;
    float m0 = -1e30f, m1 = -1e30f, l0 = 0.f, l1 = 0.f;
    const int qbase = q0 + wid*16;
    const int qr0 = qbase + g, qr1 = qr0 + 8;

    for (int kt = 0; kt < nkt; kt++) {
        const int stg = kt % 3;
        if (kt + 1 < nkt) { CPA_WAIT(1); } else { CPA_WAIT(0); }
        __syncthreads();
        if (kt == 0) {
            #pragma unroll
            for (int ks = 0; ks < 4; ks++) {
                LDMX4(qah[ks], a_addr(smb + AQ_H, wid*16, ks*32, lane, 144));
                LDMX4(qal[ks], a_addr(smb + AQ_L, wid*16, ks*32, lane, 144));
            }
        }
        if (kt + 2 < nkt) {
            load_kv(kt + 2, (kt + 2) % 3);
            CPA_COMMIT();
        }

        // ---- S = Q @ K^T (pre-scaled) ----
        float s[8][4];
        #pragma unroll
        for (int i = 0; i < 8; i++)
            #pragma unroll
            for (int j = 0; j < 4; j++) s[i][j] = 0.f;
        const uint32_t kb = smb + AK + stg*18432;
        #pragma unroll
        for (int ks = 0; ks < 4; ks++) {
            #pragma unroll
            for (int ntp = 0; ntp < 4; ntp++) {
                uint32_t bh4[4], bl4[4];
                const uint32_t ka = kb +
                    (uint32_t)(ntp*16 + (lane & 7) + ((lane >> 4) << 3)) * 144
                    + ks*32 + (((lane >> 3) & 1) << 4);
                LDMX4(bh4, ka);
                LDMX4(bl4, ka + 9216);
                MMA3(s[2*ntp],     qah[ks], qal[ks], bh4,     bl4);
                MMA3(s[2*ntp + 1], qah[ks], qal[ks], bh4 + 2, bl4 + 2);
            }
        }

        // ---- mask (interior tiles skip compares) + in-warp online softmax ----
        float mx0 = -1e30f, mx1 = -1e30f;
        if (kt*64 + 63 <= qbase) {
            #pragma unroll
            for (int nt = 0; nt < 8; nt++) {
                mx0 = fmaxf(mx0, fmaxf(s[nt][0], s[nt][1]));
                mx1 = fmaxf(mx1, fmaxf(s[nt][2], s[nt][3]));
            }
        } else {
            #pragma unroll
            for (int nt = 0; nt < 8; nt++) {
                const int c = kt*64 + nt*8 + 2*t;
                s[nt][0] = (c     <= qr0) ? s[nt][0] : -1e30f;
                s[nt][1] = (c + 1 <= qr0) ? s[nt][1] : -1e30f;
                s[nt][2] = (c     <= qr1) ? s[nt][2] : -1e30f;
                s[nt][3] = (c + 1 <= qr1) ? s[nt][3] : -1e30f;
                mx0 = fmaxf(mx0, fmaxf(s[nt][0], s[nt][1]));
                mx1 = fmaxf(mx1, fmaxf(s[nt][2], s[nt][3]));
            }
        }
        mx0 = fmaxf(mx0, __shfl_xor_sync(0xffffffffu, mx0, 1));
        mx0 = fmaxf(mx0, __shfl_xor_sync(0xffffffffu, mx0, 2));
        mx1 = fmaxf(mx1, __shfl_xor_sync(0xffffffffu, mx1, 1));
        mx1 = fmaxf(mx1, __shfl_xor_sync(0xffffffffu, mx1, 2));
        const float mn0 = fmaxf(m0, mx0), mn1 = fmaxf(m1, mx1);
        const float sc0 = __expf(m0 - mn0), sc1 = __expf(m1 - mn1);
        float sum0 = 0.f, sum1 = 0.f;
        #pragma unroll
        for (int nt = 0; nt < 8; nt++) {
            s[nt][0] = __expf(s[nt][0] - mn0);
            s[nt][1] = __expf(s[nt][1] - mn0);
            s[nt][2] = __expf(s[nt][2] - mn1);
            s[nt][3] = __expf(s[nt][3] - mn1);
            sum0 += s[nt][0] + s[nt][1];
            sum1 += s[nt][2] + s[nt][3];
        }
        sum0 += __shfl_xor_sync(0xffffffffu, sum0, 1);
        sum0 += __shfl_xor_sync(0xffffffffu, sum0, 2);
        sum1 += __shfl_xor_sync(0xffffffffu, sum1, 1);
        sum1 += __shfl_xor_sync(0xffffffffu, sum1, 2);
        l0 = l0*sc0 + sum0; l1 = l1*sc1 + sum1;
        m0 = mn0; m1 = mn1;

        // ---- pack P A-fragments (hi/lo) ----
        uint32_t ph[4][4], pl[4][4];
        #pragma unroll
        for (int ks = 0; ks < 4; ks++) {
            ph[ks][0] = packsplit2(s[2*ks][0],     s[2*ks][1],     pl[ks][0]);
            ph[ks][1] = packsplit2(s[2*ks][2],     s[2*ks][3],     pl[ks][1]);
            ph[ks][2] = packsplit2(s[2*ks + 1][0], s[2*ks + 1][1], pl[ks][2]);
            ph[ks][3] = packsplit2(s[2*ks + 1][2], s[2*ks + 1][3], pl[ks][3]);
        }

        // ---- rescale O, O += P @ V ----
        #pragma unroll
        for (int nt = 0; nt < 16; nt++) {
            o[nt][0] *= sc0; o[nt][1] *= sc0;
            o[nt][2] *= sc1; o[nt][3] *= sc1;
        }
        const uint32_t vb = smb + AV + stg*34816;
        #pragma unroll
        for (int ks = 0; ks < 4; ks++) {
            #pragma unroll
            for (int ntp = 0; ntp < 8; ntp++) {
                uint32_t vh4[4], vl4[4];
                const uint32_t va = vb +
                    (uint32_t)(ks*16 + (lane & 7) + (((lane >> 3) & 1) << 3)) * 272
                    + (ntp*16 + ((lane >> 4) << 3)) * 2;
                LDMX4T(vh4, va);
                LDMX4T(vl4, va + 17408);
                MMA3(o[2*ntp],     ph[ks], pl[ks], vh4,     vl4);
                MMA3(o[2*ntp + 1], ph[ks], pl[ks], vh4 + 2, vl4 + 2);
            }
        }
    }

    // ---- normalize + store ----
    const float i0 = 1.f / l0, i1 = 1.f / l1;
    const int r0 = wid*16 + g;
    #pragma unroll
    for (int nt = 0; nt < 16; nt++) {
        const int c = d0 + nt*8 + 2*t;
        float2 v0 = make_float2(o[nt][0]*i0, o[nt][1]*i0);
        float2 v1 = make_float2(o[nt][2]*i1, o[nt][3]*i1);
        *(float2*)(out + (tok0 + q0 + r0)     * EMB + c) = v0;
        *(float2*)(out + (tok0 + q0 + r0 + 8) * EMB + c) = v1;
    }
}

// ===========================================================================
extern "C" void kernel_launch(void* const* d_in, const int* in_sizes, int n_in,
                              void* d_out, int out_size)
{
    const float* x  = (const float*)d_in[0];
    const float* Wk = (const float*)d_in[1];
    const float* Wq = (const float*)d_in[2];
    const float* Wv = (const float*)d_in[3];
    float* out = (float*)d_out;

    __nv_bfloat16 *Qh, *Ql, *Kh, *Kl, *Vh, *Vl;
    cudaGetSymbolAddress((void**)&Qh, g_Qh);
    cudaGetSymbolAddress((void**)&Ql, g_Ql);
    cudaGetSymbolAddress((void**)&Kh, g_Kh);
    cudaGetSymbolAddress((void**)&Kl, g_Kl);
    cudaGetSymbolAddress((void**)&Vh, g_Vh);
    cudaGetSymbolAddress((void**)&Vl, g_Vl);

    cudaFuncSetAttribute(proj_tf32, cudaFuncAttributeMaxDynamicSharedMemorySize, VP_SMEM);
    cudaFuncSetAttribute(attn_reg,  cudaFuncAttributeMaxDynamicSharedMemorySize, A_SMEM);

    // Balanced V + K|Q projections (tf32), 2-stage pipeline, 2 CTAs/SM
    proj_tf32<<<dim3(9, BT/128), 256, VP_SMEM>>>(
        x, Wv, Wk, Wq, Vh, Vl, Kh, Kl, Qh, Ql);

    // Flash attention, register P
    attn_reg<<<dim3(EMB/128, SEQ/128, BATCH), 256, A_SMEM>>>(
        Qh, Ql, Kh, Kl, Vh, Vl, out);
}